// round 6
// baseline (speedup 1.0000x reference)
#include <cuda_runtime.h>
#include <math.h>

// Problem constants (fixed shapes from reference)
#define CIN   256
#define COUT  512
#define HWSZ  3136          // 56*56 ; 3136 % 64 == 0
#define BATCH 32
#define NTOT  (BATCH*HWSZ)  // 100352 = 784 * 128
#define NGRP  32
#define CPG   (COUT/NGRP)   // 16
#define GELEMS (CPG*HWSZ)   // 50176
#define EPS_GN 1e-5f
#define HT_MIN -2.0f
#define HT_MAX  2.0f

__device__ float g_mean[BATCH*NGRP];
__device__ float g_rstd[BATCH*NGRP];

// ---------------------------------------------------------------------------
// GEMM  y[b,o,hw] = sum_c W[o,c] * x[b,c,hw],  n = b*HWSZ+hw flattened.
// BM=256 x BN=128, BK=8, 256 threads, 16x8 micro-tile in split fragments:
//   rows: {ty*8..+7} and {128+ty*8..+7}   (A reads are warp-broadcast)
//   cols: {tx*4..+3} and {64+tx*4..+3}    (B reads 16B lane stride: conflict-free)
// 6 LDS.128 per 128 FMAs = 0.75 B/FMA < 128 B/cyc crossbar at peak FMA.
// Double-buffered smem.
// ---------------------------------------------------------------------------
#define BM 256
#define BN 128
#define BK 8
#define APAD 4   // As row pitch 260 floats = 1040 B, 16B-aligned, staggers banks

__global__ __launch_bounds__(256, 1)
void gemm_kernel(const float* __restrict__ x,
                 const float* __restrict__ W,
                 float* __restrict__ y)
{
    __shared__ float As[2][BK][BM + APAD];
    __shared__ float Bs[2][BK][BN];

    const int tid = threadIdx.x;
    const int m0 = blockIdx.y * BM;
    const int n0 = blockIdx.x * BN;
    const int tx = tid & 15;           // 0..15 -> n
    const int ty = tid >> 4;           // 0..15 -> m

    // A load: 256 rows x 8 cols = 2048 floats -> 2 float4 / thread
    const int a_r = tid >> 1;                  // 0..127 (also +128)
    const int a_c = (tid & 1) * 4;             // 0 or 4
    const float* wptr0 = W + (size_t)(m0 + a_r) * CIN + a_c;
    const float* wptr1 = W + (size_t)(m0 + 128 + a_r) * CIN + a_c;

    // B load: 8 rows(c) x 128 cols(n) = 1024 floats -> 1 float4 / thread
    const int b_c = tid >> 5;                  // 0..7
    const int b_n = (tid & 31) * 4;            // 0..124
    const int nB  = n0 + b_n;
    const int bbB = nB / HWSZ;
    const int hwB = nB - bbB * HWSZ;
    const float* xptr = x + ((size_t)bbB * CIN + b_c) * HWSZ + hwB;

    float acc[16][8];
    #pragma unroll
    for (int i = 0; i < 16; i++)
        #pragma unroll
        for (int j = 0; j < 8; j++)
            acc[i][j] = 0.0f;

    // ---- prologue ----
    {
        float4 a0 = *(const float4*)(wptr0);
        float4 a1 = *(const float4*)(wptr1);
        As[0][a_c + 0][a_r]       = a0.x;
        As[0][a_c + 1][a_r]       = a0.y;
        As[0][a_c + 2][a_r]       = a0.z;
        As[0][a_c + 3][a_r]       = a0.w;
        As[0][a_c + 0][a_r + 128] = a1.x;
        As[0][a_c + 1][a_r + 128] = a1.y;
        As[0][a_c + 2][a_r + 128] = a1.z;
        As[0][a_c + 3][a_r + 128] = a1.w;
        *(float4*)&Bs[0][b_c][b_n] = *(const float4*)(xptr);
    }
    __syncthreads();

    int cur = 0;
    for (int k0 = 0; k0 < CIN; k0 += BK) {
        float4 a0, a1, bv;
        const bool more = (k0 + BK) < CIN;
        if (more) {
            a0 = *(const float4*)(wptr0 + (k0 + BK));
            a1 = *(const float4*)(wptr1 + (k0 + BK));
            bv = *(const float4*)(xptr + (size_t)(k0 + BK) * HWSZ);
        }

        #pragma unroll
        for (int kk = 0; kk < BK; kk++) {
            float a[16], b[8];
            *(float4*)(a + 0)  = *(const float4*)&As[cur][kk][ty * 8 + 0];
            *(float4*)(a + 4)  = *(const float4*)&As[cur][kk][ty * 8 + 4];
            *(float4*)(a + 8)  = *(const float4*)&As[cur][kk][128 + ty * 8 + 0];
            *(float4*)(a + 12) = *(const float4*)&As[cur][kk][128 + ty * 8 + 4];
            *(float4*)(b + 0)  = *(const float4*)&Bs[cur][kk][tx * 4];
            *(float4*)(b + 4)  = *(const float4*)&Bs[cur][kk][64 + tx * 4];
            #pragma unroll
            for (int i = 0; i < 16; i++)
                #pragma unroll
                for (int j = 0; j < 8; j++)
                    acc[i][j] = fmaf(a[i], b[j], acc[i][j]);
        }

        if (more) {
            const int nxt = cur ^ 1;
            As[nxt][a_c + 0][a_r]       = a0.x;
            As[nxt][a_c + 1][a_r]       = a0.y;
            As[nxt][a_c + 2][a_r]       = a0.z;
            As[nxt][a_c + 3][a_r]       = a0.w;
            As[nxt][a_c + 0][a_r + 128] = a1.x;
            As[nxt][a_c + 1][a_r + 128] = a1.y;
            As[nxt][a_c + 2][a_r + 128] = a1.z;
            As[nxt][a_c + 3][a_r + 128] = a1.w;
            *(float4*)&Bs[nxt][b_c][b_n] = bv;
        }
        __syncthreads();
        cur ^= 1;
    }

    // ---- epilogue: 4 quadrants, each col-half stays within one batch ----
    #pragma unroll
    for (int ch = 0; ch < 2; ch++) {
        const int nc  = n0 + ch * 64 + tx * 4;
        const int bb  = nc / HWSZ;
        const int hw  = nc - bb * HWSZ;
        #pragma unroll
        for (int cl = 0; cl < 2; cl++) {
            #pragma unroll
            for (int i = 0; i < 8; i++) {
                const int row = m0 + cl * 128 + ty * 8 + i;
                float* yp = y + ((size_t)bb * COUT + row) * HWSZ + hw;
                *(float4*)yp = make_float4(acc[cl * 8 + i][ch * 4 + 0],
                                           acc[cl * 8 + i][ch * 4 + 1],
                                           acc[cl * 8 + i][ch * 4 + 2],
                                           acc[cl * 8 + i][ch * 4 + 3]);
            }
        }
    }
}

// ---------------------------------------------------------------------------
// GroupNorm statistics. One block per (b,g); group span is contiguous.
// ---------------------------------------------------------------------------
__global__ __launch_bounds__(256)
void stats_kernel(const float* __restrict__ y)
{
    const int bg = blockIdx.x;
    const float4* p = (const float4*)(y + (size_t)bg * GELEMS);
    const int n4 = GELEMS / 4;

    float s = 0.0f, ss = 0.0f;
    for (int i = threadIdx.x; i < n4; i += 256) {
        float4 v = p[i];
        s  += (v.x + v.y) + (v.z + v.w);
        ss += (v.x * v.x + v.y * v.y) + (v.z * v.z + v.w * v.w);
    }
    #pragma unroll
    for (int o = 16; o > 0; o >>= 1) {
        s  += __shfl_down_sync(0xffffffffu, s, o);
        ss += __shfl_down_sync(0xffffffffu, ss, o);
    }
    __shared__ float ws[8], wss[8];
    const int lane = threadIdx.x & 31, wid = threadIdx.x >> 5;
    if (lane == 0) { ws[wid] = s; wss[wid] = ss; }
    __syncthreads();
    if (wid == 0) {
        s  = (lane < 8) ? ws[lane]  : 0.0f;
        ss = (lane < 8) ? wss[lane] : 0.0f;
        #pragma unroll
        for (int o = 4; o > 0; o >>= 1) {
            s  += __shfl_down_sync(0xffffffffu, s, o);
            ss += __shfl_down_sync(0xffffffffu, ss, o);
        }
        if (lane == 0) {
            const float inv_n = 1.0f / (float)GELEMS;
            float mean = s * inv_n;
            float var  = ss * inv_n - mean * mean;
            g_mean[bg] = mean;
            g_rstd[bg] = rsqrtf(var + EPS_GN);
        }
    }
}

// ---------------------------------------------------------------------------
// normalize + affine + hardtanh, in place, float4.
// ---------------------------------------------------------------------------
__global__ __launch_bounds__(256)
void norm_kernel(float* __restrict__ y,
                 const float* __restrict__ gamma,
                 const float* __restrict__ beta)
{
    const size_t i4  = (size_t)blockIdx.x * 256 + threadIdx.x;
    const size_t idx = i4 * 4;
    const int o  = (int)((idx / HWSZ) % COUT);
    const int bg = (int)(idx / GELEMS);

    const float r  = g_rstd[bg];
    const float ga = gamma[o] * r;
    const float be = beta[o] - g_mean[bg] * ga;

    float4 v = *(float4*)(y + idx);
    v.x = fminf(fmaxf(fmaf(v.x, ga, be), HT_MIN), HT_MAX);
    v.y = fminf(fmaxf(fmaf(v.y, ga, be), HT_MIN), HT_MAX);
    v.z = fminf(fmaxf(fmaf(v.z, ga, be), HT_MIN), HT_MAX);
    v.w = fminf(fmaxf(fmaf(v.w, ga, be), HT_MIN), HT_MAX);
    *(float4*)(y + idx) = v;
}

// ---------------------------------------------------------------------------
extern "C" void kernel_launch(void* const* d_in, const int* in_sizes, int n_in,
                              void* d_out, int out_size)
{
    const float* x     = (const float*)d_in[0];
    const float* W     = (const float*)d_in[1];
    const float* gamma = (const float*)d_in[2];
    const float* beta  = (const float*)d_in[3];
    float* y = (float*)d_out;

    dim3 ggrid(NTOT / BN, COUT / BM);            // (784, 2)
    gemm_kernel<<<ggrid, 256>>>(x, W, y);

    stats_kernel<<<BATCH * NGRP, 256>>>(y);

    const size_t total4 = (size_t)BATCH * COUT * HWSZ / 4;
    norm_kernel<<<(unsigned)(total4 / 256), 256>>>(y, gamma, beta);
}

// round 7
// speedup vs baseline: 1.1625x; 1.1625x over previous
#include <cuda_runtime.h>
#include <math.h>

// Problem constants (fixed shapes from reference)
#define CIN   256
#define COUT  512
#define HWSZ  3136          // 56*56 ; 3136 % 64 == 0
#define BATCH 32
#define NTOT  (BATCH*HWSZ)  // 100352 = 784 * 128
#define NGRP  32
#define CPG   (COUT/NGRP)   // 16
#define GELEMS (CPG*HWSZ)   // 50176
#define EPS_GN 1e-5f
#define HT_MIN -2.0f
#define HT_MAX  2.0f

__device__ float g_mean[BATCH*NGRP];
__device__ float g_rstd[BATCH*NGRP];

// ---------------------------------------------------------------------------
// GEMM  y[b,o,hw] = sum_c W[o,c] * x[b,c,hw],  n = b*HWSZ+hw flattened.
// BM=128 x BN=128, BK=8, 256 threads, 8x8 micro-tile. regs~128 -> 2 CTA/SM
// (16 warps: R6 evidence says this occupancy is needed to cover latency).
// B fragment SPLIT: cols {tx*4..+3} and {64+tx*4..+3} -> 16B lane stride
// within each LDS.128 phase -> conflict-free (fixes R3's L1=86.8% ceiling).
// A fragment rows {ty*8..+7}: warp-broadcast, free.
// Double-buffered smem.
// ---------------------------------------------------------------------------
#define BM 128
#define BN 128
#define BK 8

__global__ __launch_bounds__(256, 2)
void gemm_kernel(const float* __restrict__ x,
                 const float* __restrict__ W,
                 float* __restrict__ y)
{
    __shared__ float As[2][BK][BM + 4];   // pitch 132 floats = 528B, 16B-aligned
    __shared__ float Bs[2][BK][BN];

    const int tid = threadIdx.x;
    const int m0 = blockIdx.y * BM;
    const int n0 = blockIdx.x * BN;
    const int tx = tid & 15;           // 0..15 -> n micro-tile
    const int ty = tid >> 4;           // 0..15 -> m micro-tile

    // A (weight) load mapping: 128 rows x 8 cols, float4/thread
    const int a_o = tid >> 1;          // 0..127
    const int a_c = (tid & 1) * 4;     // 0 or 4
    const float* wptr = W + (size_t)(m0 + a_o) * CIN + a_c;

    // B (x) load mapping: 8 rows(c) x 128 cols(n), float4/thread
    const int b_c = tid >> 5;          // 0..7
    const int b_n = (tid & 31) * 4;    // 0..124
    const int nB  = n0 + b_n;
    const int bbB = nB / HWSZ;
    const int hwB = nB - bbB * HWSZ;
    const float* xptr = x + ((size_t)bbB * CIN + b_c) * HWSZ + hwB;

    float acc[8][8];
    #pragma unroll
    for (int i = 0; i < 8; i++)
        #pragma unroll
        for (int j = 0; j < 8; j++)
            acc[i][j] = 0.0f;

    // ---- prologue: tile 0 -> buffer 0 ----
    {
        float4 av = *(const float4*)(wptr);
        As[0][a_c + 0][a_o] = av.x;
        As[0][a_c + 1][a_o] = av.y;
        As[0][a_c + 2][a_o] = av.z;
        As[0][a_c + 3][a_o] = av.w;
        *(float4*)&Bs[0][b_c][b_n] = *(const float4*)(xptr);
    }
    __syncthreads();

    int cur = 0;
    for (int k0 = 0; k0 < CIN; k0 += BK) {
        float4 av, bv;
        const bool more = (k0 + BK) < CIN;
        if (more) {
            av = *(const float4*)(wptr + (k0 + BK));
            bv = *(const float4*)(xptr + (size_t)(k0 + BK) * HWSZ);
        }

        #pragma unroll
        for (int kk = 0; kk < BK; kk++) {
            float a[8], b[8];
            *(float4*)(a + 0) = *(const float4*)&As[cur][kk][ty * 8 + 0];
            *(float4*)(a + 4) = *(const float4*)&As[cur][kk][ty * 8 + 4];
            // split B fragment: 16B lane stride per phase -> conflict-free
            *(float4*)(b + 0) = *(const float4*)&Bs[cur][kk][tx * 4];
            *(float4*)(b + 4) = *(const float4*)&Bs[cur][kk][64 + tx * 4];
            #pragma unroll
            for (int i = 0; i < 8; i++)
                #pragma unroll
                for (int j = 0; j < 8; j++)
                    acc[i][j] = fmaf(a[i], b[j], acc[i][j]);
        }

        if (more) {
            const int nxt = cur ^ 1;
            As[nxt][a_c + 0][a_o] = av.x;
            As[nxt][a_c + 1][a_o] = av.y;
            As[nxt][a_c + 2][a_o] = av.z;
            As[nxt][a_c + 3][a_o] = av.w;
            *(float4*)&Bs[nxt][b_c][b_n] = bv;
        }
        __syncthreads();
        cur ^= 1;
    }

    // ---- epilogue: two 4-col halves; each half stays within one batch ----
    #pragma unroll
    for (int ch = 0; ch < 2; ch++) {
        const int nc = n0 + ch * 64 + tx * 4;
        const int bb = nc / HWSZ;
        const int hw = nc - bb * HWSZ;
        #pragma unroll
        for (int i = 0; i < 8; i++) {
            float* yp = y + ((size_t)bb * COUT + (m0 + ty * 8 + i)) * HWSZ + hw;
            *(float4*)yp = make_float4(acc[i][ch * 4 + 0],
                                       acc[i][ch * 4 + 1],
                                       acc[i][ch * 4 + 2],
                                       acc[i][ch * 4 + 3]);
        }
    }
}

// ---------------------------------------------------------------------------
// GroupNorm statistics. One block per (b,g); group span is contiguous.
// ---------------------------------------------------------------------------
__global__ __launch_bounds__(256)
void stats_kernel(const float* __restrict__ y)
{
    const int bg = blockIdx.x;
    const float4* p = (const float4*)(y + (size_t)bg * GELEMS);
    const int n4 = GELEMS / 4;

    float s = 0.0f, ss = 0.0f;
    for (int i = threadIdx.x; i < n4; i += 256) {
        float4 v = p[i];
        s  += (v.x + v.y) + (v.z + v.w);
        ss += (v.x * v.x + v.y * v.y) + (v.z * v.z + v.w * v.w);
    }
    #pragma unroll
    for (int o = 16; o > 0; o >>= 1) {
        s  += __shfl_down_sync(0xffffffffu, s, o);
        ss += __shfl_down_sync(0xffffffffu, ss, o);
    }
    __shared__ float ws[8], wss[8];
    const int lane = threadIdx.x & 31, wid = threadIdx.x >> 5;
    if (lane == 0) { ws[wid] = s; wss[wid] = ss; }
    __syncthreads();
    if (wid == 0) {
        s  = (lane < 8) ? ws[lane]  : 0.0f;
        ss = (lane < 8) ? wss[lane] : 0.0f;
        #pragma unroll
        for (int o = 4; o > 0; o >>= 1) {
            s  += __shfl_down_sync(0xffffffffu, s, o);
            ss += __shfl_down_sync(0xffffffffu, ss, o);
        }
        if (lane == 0) {
            const float inv_n = 1.0f / (float)GELEMS;
            float mean = s * inv_n;
            float var  = ss * inv_n - mean * mean;
            g_mean[bg] = mean;
            g_rstd[bg] = rsqrtf(var + EPS_GN);
        }
    }
}

// ---------------------------------------------------------------------------
// normalize + affine + hardtanh, in place, float4.
// ---------------------------------------------------------------------------
__global__ __launch_bounds__(256)
void norm_kernel(float* __restrict__ y,
                 const float* __restrict__ gamma,
                 const float* __restrict__ beta)
{
    const size_t i4  = (size_t)blockIdx.x * 256 + threadIdx.x;
    const size_t idx = i4 * 4;
    const int o  = (int)((idx / HWSZ) % COUT);
    const int bg = (int)(idx / GELEMS);

    const float r  = g_rstd[bg];
    const float ga = gamma[o] * r;
    const float be = beta[o] - g_mean[bg] * ga;

    float4 v = *(float4*)(y + idx);
    v.x = fminf(fmaxf(fmaf(v.x, ga, be), HT_MIN), HT_MAX);
    v.y = fminf(fmaxf(fmaf(v.y, ga, be), HT_MIN), HT_MAX);
    v.z = fminf(fmaxf(fmaf(v.z, ga, be), HT_MIN), HT_MAX);
    v.w = fminf(fmaxf(fmaf(v.w, ga, be), HT_MIN), HT_MAX);
    *(float4*)(y + idx) = v;
}

// ---------------------------------------------------------------------------
extern "C" void kernel_launch(void* const* d_in, const int* in_sizes, int n_in,
                              void* d_out, int out_size)
{
    const float* x     = (const float*)d_in[0];
    const float* W     = (const float*)d_in[1];
    const float* gamma = (const float*)d_in[2];
    const float* beta  = (const float*)d_in[3];
    float* y = (float*)d_out;

    dim3 ggrid(NTOT / BN, COUT / BM);            // (784, 4)
    gemm_kernel<<<ggrid, 256>>>(x, W, y);

    stats_kernel<<<BATCH * NGRP, 256>>>(y);

    const size_t total4 = (size_t)BATCH * COUT * HWSZ / 4;
    norm_kernel<<<(unsigned)(total4 / 256), 256>>>(y, gamma, beta);
}

// round 11
// speedup vs baseline: 1.4369x; 1.2361x over previous
#include <cuda_runtime.h>
#include <cuda_bf16.h>
#include <math.h>
#include <cstdint>

// Problem constants
#define CIN   256
#define COUT  512
#define HWSZ  3136
#define BATCH 32
#define NTOT  (BATCH*HWSZ)   // 100352
#define NGRP  32
#define CPG   (COUT/NGRP)
#define GELEMS (CPG*HWSZ)
#define EPS_GN 1e-5f
#define HT_MIN -2.0f
#define HT_MAX  2.0f

// Device-global scratch (sanctioned no-alloc path)
__device__ float g_mean[BATCH*NGRP];
__device__ float g_rstd[BATCH*NGRP];
__device__ __align__(16) __nv_bfloat16 g_x_hi[(size_t)CIN*NTOT];  // [c][n], 51.4MB
__device__ __align__(16) __nv_bfloat16 g_x_lo[(size_t)CIN*NTOT];
__device__ __align__(16) __nv_bfloat16 g_w_hi[COUT*CIN];          // [o][c]
__device__ __align__(16) __nv_bfloat16 g_w_lo[COUT*CIN];

// ---------------- warp-level MMA helpers (sm_80+ baseline ISA) ----------------
__device__ __forceinline__ uint32_t smem_u32(const void* p) {
    uint32_t a;
    asm("{ .reg .u64 t; cvta.to.shared.u64 t, %1; cvt.u32.u64 %0, t; }" : "=r"(a) : "l"(p));
    return a;
}
__device__ __forceinline__ void ldsm_x4(uint32_t* r, uint32_t addr) {
    asm volatile("ldmatrix.sync.aligned.m8n8.x4.shared.b16 {%0,%1,%2,%3}, [%4];"
        : "=r"(r[0]), "=r"(r[1]), "=r"(r[2]), "=r"(r[3]) : "r"(addr));
}
__device__ __forceinline__ void ldsm_x4_t(uint32_t* r, uint32_t addr) {
    asm volatile("ldmatrix.sync.aligned.m8n8.x4.trans.shared.b16 {%0,%1,%2,%3}, [%4];"
        : "=r"(r[0]), "=r"(r[1]), "=r"(r[2]), "=r"(r[3]) : "r"(addr));
}
__device__ __forceinline__ void mma_bf16(float* d, const uint32_t* a, const uint32_t* b) {
    asm volatile("mma.sync.aligned.m16n8k16.row.col.f32.bf16.bf16.f32 "
        "{%0,%1,%2,%3}, {%4,%5,%6,%7}, {%8,%9}, {%0,%1,%2,%3};"
        : "+f"(d[0]), "+f"(d[1]), "+f"(d[2]), "+f"(d[3])
        : "r"(a[0]), "r"(a[1]), "r"(a[2]), "r"(a[3]), "r"(b[0]), "r"(b[1]));
}

// ---------------------------------------------------------------------------
// Conversion: fp32 -> bf16 hi/lo split (lo = v - hi is exact in fp32)
// ---------------------------------------------------------------------------
__global__ void convert_w_kernel(const float* __restrict__ W) {
    int i = blockIdx.x * 256 + threadIdx.x;       // COUT*CIN = 131072
    float v = W[i];
    __nv_bfloat16 hi = __float2bfloat16(v);
    g_w_hi[i] = hi;
    g_w_lo[i] = __float2bfloat16(v - __bfloat162float(hi));
}

// x [b][c][hw] -> g_x [c][b*HWSZ+hw]  (pure relayout, coalesced both sides)
__global__ void convert_x_kernel(const float* __restrict__ x) {
    const int n = blockIdx.x * 256 + threadIdx.x;    // 0..NTOT-1
    const int c = blockIdx.y;
    const int b = n / HWSZ, hw = n - b * HWSZ;
    float v = x[((size_t)b * CIN + c) * HWSZ + hw];
    __nv_bfloat16 hi = __float2bfloat16(v);
    const size_t o = (size_t)c * NTOT + n;
    g_x_hi[o] = hi;
    g_x_lo[o] = __float2bfloat16(v - __bfloat162float(hi));
}

// ---------------------------------------------------------------------------
// Tensor-core GEMM via mma.sync: y[b,o,hw] = sum_c W[o,c]*x[b,c,hw]
// CTA: 128(cout) x 128(spatial) x BK=32. 8 warps = 4(m) x 2(n); warp 32x64.
// A = W tile [m][k] (ldmatrix non-trans), B = x tile [k][n] (ldmatrix trans).
// 3-pass split precision: hh + hl + lh (lo*lo dropped, ~2^-18 rel).
// ---------------------------------------------------------------------------
#define PA 40    // A smem pitch (halves): 80B rows -> conflict-free ldmatrix
#define PB 136   // B smem pitch (halves): 272B rows -> conflict-free ldmatrix

__global__ __launch_bounds__(256)
void gemm_mma_kernel(float* __restrict__ y)
{
    __shared__ __align__(16) __nv_bfloat16 sA[2][128][PA];   // [prec][m][k]
    __shared__ __align__(16) __nv_bfloat16 sB[2][32][PB];    // [prec][k][n]

    const int tid  = threadIdx.x;
    const int lane = tid & 31;
    const int w    = tid >> 5;
    const int wm   = (w & 3) * 32;          // warp m offset (cout)
    const int wn   = (w >> 2) * 64;         // warp n offset (spatial)
    const int o0   = blockIdx.x * 128;      // cout tile (fast dim -> x reuse in L2)
    const int n0   = blockIdx.y * 128;      // spatial tile

    float acc[2][8][4];
    #pragma unroll
    for (int i = 0; i < 2; i++)
        #pragma unroll
        for (int j = 0; j < 8; j++)
            #pragma unroll
            for (int q = 0; q < 4; q++) acc[i][j][q] = 0.0f;

    for (int kb = 0; kb < CIN / 32; kb++) {
        __syncthreads();
        // load A tiles (W hi/lo): 128x32 halves per prec = 512 uint4
        #pragma unroll
        for (int q = 0; q < 2; q++) {
            int i = tid + q * 256;
            int row = i >> 2, c16 = i & 3;
            size_t ge = (size_t)(o0 + row) * CIN + kb * 32 + c16 * 8;
            *(uint4*)&sA[0][row][c16 * 8] = *(const uint4*)(g_w_hi + ge);
            *(uint4*)&sA[1][row][c16 * 8] = *(const uint4*)(g_w_lo + ge);
        }
        // load B tiles (x hi/lo): 32x128 halves per prec = 512 uint4
        #pragma unroll
        for (int q = 0; q < 2; q++) {
            int i = tid + q * 256;
            int row = i >> 4, c16 = i & 15;
            size_t ge = (size_t)(kb * 32 + row) * NTOT + n0 + c16 * 8;
            *(uint4*)&sB[0][row][c16 * 8] = *(const uint4*)(g_x_hi + ge);
            *(uint4*)&sB[1][row][c16 * 8] = *(const uint4*)(g_x_lo + ge);
        }
        __syncthreads();

        #pragma unroll
        for (int ks = 0; ks < 2; ks++) {          // two k16 steps per block
            uint32_t ah[2][4], al[2][4];
            #pragma unroll
            for (int mi = 0; mi < 2; mi++) {
                const int r = wm + mi * 16 + (lane & 15);
                const int c = ks * 16 + (lane >> 4) * 8;
                ldsm_x4(ah[mi], smem_u32(&sA[0][r][c]));
                ldsm_x4(al[mi], smem_u32(&sA[1][r][c]));
            }
            uint32_t bh[4][4], bl[4][4];
            #pragma unroll
            for (int nj = 0; nj < 4; nj++) {      // 4 x n16 groups = warp n64
                const int r = ks * 16 + (lane & 15);
                const int c = wn + nj * 16 + (lane >> 4) * 8;
                ldsm_x4_t(bh[nj], smem_u32(&sB[0][r][c]));
                ldsm_x4_t(bl[nj], smem_u32(&sB[1][r][c]));
            }
            #pragma unroll
            for (int mi = 0; mi < 2; mi++)
                #pragma unroll
                for (int nj = 0; nj < 4; nj++)
                    #pragma unroll
                    for (int h = 0; h < 2; h++) {
                        float* d = acc[mi][nj * 2 + h];
                        mma_bf16(d, ah[mi], bh[nj] + h * 2);   // hi*hi
                        mma_bf16(d, ah[mi], bl[nj] + h * 2);   // hi*lo
                        mma_bf16(d, al[mi], bh[nj] + h * 2);   // lo*hi
                    }
        }
    }

    // epilogue: warp n-span 64 within one batch (HWSZ % 64 == 0)
    const int ng = n0 + wn;
    const int bb = ng / HWSZ;
    const int hwb = ng - bb * HWSZ + (lane & 3) * 2;
    const int rg = o0 + wm + (lane >> 2);
    #pragma unroll
    for (int mi = 0; mi < 2; mi++) {
        #pragma unroll
        for (int nf = 0; nf < 8; nf++) {
            const int hw = hwb + nf * 8;
            const float* d = acc[mi][nf];
            float* y0 = y + ((size_t)bb * COUT + rg + mi * 16) * HWSZ + hw;
            *(float2*)y0               = make_float2(d[0], d[1]);
            *(float2*)(y0 + 8 * HWSZ)  = make_float2(d[2], d[3]);
        }
    }
}

// ---------------------------------------------------------------------------
// GroupNorm stats + normalize (measured near DRAM roofline, unchanged)
// ---------------------------------------------------------------------------
__global__ __launch_bounds__(256)
void stats_kernel(const float* __restrict__ y)
{
    const int bg = blockIdx.x;
    const float4* p = (const float4*)(y + (size_t)bg * GELEMS);
    const int n4 = GELEMS / 4;
    float s = 0.0f, ss = 0.0f;
    for (int i = threadIdx.x; i < n4; i += 256) {
        float4 v = p[i];
        s  += (v.x + v.y) + (v.z + v.w);
        ss += (v.x * v.x + v.y * v.y) + (v.z * v.z + v.w * v.w);
    }
    #pragma unroll
    for (int o = 16; o > 0; o >>= 1) {
        s  += __shfl_down_sync(0xffffffffu, s, o);
        ss += __shfl_down_sync(0xffffffffu, ss, o);
    }
    __shared__ float ws[8], wss[8];
    const int lane = threadIdx.x & 31, wid = threadIdx.x >> 5;
    if (lane == 0) { ws[wid] = s; wss[wid] = ss; }
    __syncthreads();
    if (wid == 0) {
        s  = (lane < 8) ? ws[lane]  : 0.0f;
        ss = (lane < 8) ? wss[lane] : 0.0f;
        #pragma unroll
        for (int o = 4; o > 0; o >>= 1) {
            s  += __shfl_down_sync(0xffffffffu, s, o);
            ss += __shfl_down_sync(0xffffffffu, ss, o);
        }
        if (lane == 0) {
            const float inv_n = 1.0f / (float)GELEMS;
            float mean = s * inv_n;
            float var  = ss * inv_n - mean * mean;
            g_mean[bg] = mean;
            g_rstd[bg] = rsqrtf(var + EPS_GN);
        }
    }
}

__global__ __launch_bounds__(256)
void norm_kernel(float* __restrict__ y,
                 const float* __restrict__ gamma,
                 const float* __restrict__ beta)
{
    const size_t i4  = (size_t)blockIdx.x * 256 + threadIdx.x;
    const size_t idx = i4 * 4;
    const int o  = (int)((idx / HWSZ) % COUT);
    const int bg = (int)(idx / GELEMS);
    const float r  = g_rstd[bg];
    const float ga = gamma[o] * r;
    const float be = beta[o] - g_mean[bg] * ga;
    float4 v = *(float4*)(y + idx);
    v.x = fminf(fmaxf(fmaf(v.x, ga, be), HT_MIN), HT_MAX);
    v.y = fminf(fmaxf(fmaf(v.y, ga, be), HT_MIN), HT_MAX);
    v.z = fminf(fmaxf(fmaf(v.z, ga, be), HT_MIN), HT_MAX);
    v.w = fminf(fmaxf(fmaf(v.w, ga, be), HT_MIN), HT_MAX);
    *(float4*)(y + idx) = v;
}

// ---------------------------------------------------------------------------
extern "C" void kernel_launch(void* const* d_in, const int* in_sizes, int n_in,
                              void* d_out, int out_size)
{
    const float* x     = (const float*)d_in[0];
    const float* W     = (const float*)d_in[1];
    const float* gamma = (const float*)d_in[2];
    const float* beta  = (const float*)d_in[3];
    float* y = (float*)d_out;

    convert_w_kernel<<<COUT * CIN / 256, 256>>>(W);
    convert_x_kernel<<<dim3(NTOT / 256, CIN), 256>>>(x);
    gemm_mma_kernel<<<dim3(COUT / 128, NTOT / 128), 256>>>(y);
    stats_kernel<<<BATCH * NGRP, 256>>>(y);
    const size_t total4 = (size_t)BATCH * COUT * HWSZ / 4;
    norm_kernel<<<(unsigned)(total4 / 256), 256>>>(y, gamma, beta);
}

// round 12
// speedup vs baseline: 1.7227x; 1.1989x over previous
#include <cuda_runtime.h>
#include <cuda_bf16.h>
#include <math.h>
#include <cstdint>

// Problem constants
#define CIN   256
#define COUT  512
#define HWSZ  3136
#define BATCH 32
#define NTOT  (BATCH*HWSZ)   // 100352
#define NGRP  32
#define CPG   (COUT/NGRP)
#define GELEMS (CPG*HWSZ)
#define EPS_GN 1e-5f
#define HT_MIN -2.0f
#define HT_MAX  2.0f

// Device-global scratch (sanctioned no-alloc path)
__device__ float g_mean[BATCH*NGRP];
__device__ float g_rstd[BATCH*NGRP];
__device__ __align__(16) __nv_bfloat16 g_x_hi[(size_t)CIN*NTOT];  // [c][n]
__device__ __align__(16) __nv_bfloat16 g_x_lo[(size_t)CIN*NTOT];
__device__ __align__(16) __nv_bfloat16 g_w_hi[COUT*CIN];          // [o][c]
__device__ __align__(16) __nv_bfloat16 g_w_lo[COUT*CIN];

// ---------------- warp-level MMA helpers (sm_80+ baseline ISA) ----------------
__device__ __forceinline__ uint32_t smem_u32(const void* p) {
    uint32_t a;
    asm("{ .reg .u64 t; cvta.to.shared.u64 t, %1; cvt.u32.u64 %0, t; }" : "=r"(a) : "l"(p));
    return a;
}
__device__ __forceinline__ void ldsm_x4(uint32_t* r, uint32_t addr) {
    asm volatile("ldmatrix.sync.aligned.m8n8.x4.shared.b16 {%0,%1,%2,%3}, [%4];"
        : "=r"(r[0]), "=r"(r[1]), "=r"(r[2]), "=r"(r[3]) : "r"(addr));
}
__device__ __forceinline__ void ldsm_x4_t(uint32_t* r, uint32_t addr) {
    asm volatile("ldmatrix.sync.aligned.m8n8.x4.trans.shared.b16 {%0,%1,%2,%3}, [%4];"
        : "=r"(r[0]), "=r"(r[1]), "=r"(r[2]), "=r"(r[3]) : "r"(addr));
}
__device__ __forceinline__ void mma_bf16(float* d, const uint32_t* a, const uint32_t* b) {
    asm volatile("mma.sync.aligned.m16n8k16.row.col.f32.bf16.bf16.f32 "
        "{%0,%1,%2,%3}, {%4,%5,%6,%7}, {%8,%9}, {%0,%1,%2,%3};"
        : "+f"(d[0]), "+f"(d[1]), "+f"(d[2]), "+f"(d[3])
        : "r"(a[0]), "r"(a[1]), "r"(a[2]), "r"(a[3]), "r"(b[0]), "r"(b[1]));
}

// ---------------------------------------------------------------------------
// Conversion: fp32 -> bf16 hi/lo split (lo = v - hi is exact in fp32)
// ---------------------------------------------------------------------------
__global__ void convert_w_kernel(const float* __restrict__ W) {
    int i = blockIdx.x * 256 + threadIdx.x;       // COUT*CIN = 131072
    float v = W[i];
    __nv_bfloat16 hi = __float2bfloat16(v);
    g_w_hi[i] = hi;
    g_w_lo[i] = __float2bfloat16(v - __bfloat162float(hi));
}

// x [b][c][hw] -> g_x [c][b*HWSZ+hw]  (pure relayout, coalesced both sides)
__global__ void convert_x_kernel(const float* __restrict__ x) {
    const int n = blockIdx.x * 256 + threadIdx.x;    // 0..NTOT-1
    const int c = blockIdx.y;
    const int b = n / HWSZ, hw = n - b * HWSZ;
    float v = x[((size_t)b * CIN + c) * HWSZ + hw];
    __nv_bfloat16 hi = __float2bfloat16(v);
    const size_t o = (size_t)c * NTOT + n;
    g_x_hi[o] = hi;
    g_x_lo[o] = __float2bfloat16(v - __bfloat162float(hi));
}

// ---------------------------------------------------------------------------
// Tensor-core GEMM via mma.sync: y[b,o,hw] = sum_c W[o,c]*x[b,c,hw]
// CTA: 128(cout) x 128(spatial) x BK=32. 8 warps = 4(m) x 2(n); warp 32x64.
// A = W tile [m][k] (ldmatrix non-trans), B = x tile [k][n] (ldmatrix trans).
// 3-pass split precision: hh + hl + lh (lo*lo dropped, ~2^-18 rel).
// Register-prefetch pipeline: next k-block's LDGs issued before compute,
// stored to smem after the consume-sync -> global latency hidden.
// ---------------------------------------------------------------------------
#define PA 40    // A smem pitch (halves): 80B rows -> conflict-free ldmatrix
#define PB 136   // B smem pitch (halves): 272B rows -> conflict-free ldmatrix

__global__ __launch_bounds__(256, 1)
void gemm_mma_kernel(float* __restrict__ y)
{
    __shared__ __align__(16) __nv_bfloat16 sA[2][128][PA];   // [prec][m][k]
    __shared__ __align__(16) __nv_bfloat16 sB[2][32][PB];    // [prec][k][n]

    const int tid  = threadIdx.x;
    const int lane = tid & 31;
    const int w    = tid >> 5;
    const int wm   = (w & 3) * 32;          // warp m offset (cout)
    const int wn   = (w >> 2) * 64;         // warp n offset (spatial)
    const int o0   = blockIdx.x * 128;      // cout tile (fast dim -> x reuse in L2)
    const int n0   = blockIdx.y * 128;      // spatial tile

    // per-thread load coordinates (fixed across k-blocks)
    const int aRow = (tid & 1023) >> 2;     // reused per q with +offset via i
    // A: i = tid + q*256 -> row=i>>2 (0..127), c16=i&3
    // B: i = tid + q*256 -> row=i>>4 (0..31),  c16=i&15

    float acc[2][8][4];
    #pragma unroll
    for (int i = 0; i < 2; i++)
        #pragma unroll
        for (int j = 0; j < 8; j++)
            #pragma unroll
            for (int q = 0; q < 4; q++) acc[i][j][q] = 0.0f;
    (void)aRow;

    // ---- prologue: k-block 0 direct to smem ----
    #pragma unroll
    for (int q = 0; q < 2; q++) {
        int i = tid + q * 256;
        int row = i >> 2, c16 = i & 3;
        size_t ge = (size_t)(o0 + row) * CIN + c16 * 8;
        *(uint4*)&sA[0][row][c16 * 8] = *(const uint4*)(g_w_hi + ge);
        *(uint4*)&sA[1][row][c16 * 8] = *(const uint4*)(g_w_lo + ge);
    }
    #pragma unroll
    for (int q = 0; q < 2; q++) {
        int i = tid + q * 256;
        int row = i >> 4, c16 = i & 15;
        size_t ge = (size_t)row * NTOT + n0 + c16 * 8;
        *(uint4*)&sB[0][row][c16 * 8] = *(const uint4*)(g_x_hi + ge);
        *(uint4*)&sB[1][row][c16 * 8] = *(const uint4*)(g_x_lo + ge);
    }
    __syncthreads();

    for (int kb = 0; kb < CIN / 32; kb++) {
        const bool more = (kb + 1) < (CIN / 32);
        uint4 rAh[2], rAl[2], rBh[2], rBl[2];
        if (more) {
            #pragma unroll
            for (int q = 0; q < 2; q++) {
                int i = tid + q * 256;
                int row = i >> 2, c16 = i & 3;
                size_t ge = (size_t)(o0 + row) * CIN + (kb + 1) * 32 + c16 * 8;
                rAh[q] = *(const uint4*)(g_w_hi + ge);
                rAl[q] = *(const uint4*)(g_w_lo + ge);
            }
            #pragma unroll
            for (int q = 0; q < 2; q++) {
                int i = tid + q * 256;
                int row = i >> 4, c16 = i & 15;
                size_t ge = (size_t)((kb + 1) * 32 + row) * NTOT + n0 + c16 * 8;
                rBh[q] = *(const uint4*)(g_x_hi + ge);
                rBl[q] = *(const uint4*)(g_x_lo + ge);
            }
        }

        #pragma unroll
        for (int ks = 0; ks < 2; ks++) {          // two k16 steps per block
            uint32_t ah[2][4], al[2][4];
            #pragma unroll
            for (int mi = 0; mi < 2; mi++) {
                const int r = wm + mi * 16 + (lane & 15);
                const int c = ks * 16 + (lane >> 4) * 8;
                ldsm_x4(ah[mi], smem_u32(&sA[0][r][c]));
                ldsm_x4(al[mi], smem_u32(&sA[1][r][c]));
            }
            uint32_t bh[4][4], bl[4][4];
            #pragma unroll
            for (int nj = 0; nj < 4; nj++) {      // 4 x n16 groups = warp n64
                const int r = ks * 16 + (lane & 15);
                const int c = wn + nj * 16 + (lane >> 4) * 8;
                ldsm_x4_t(bh[nj], smem_u32(&sB[0][r][c]));
                ldsm_x4_t(bl[nj], smem_u32(&sB[1][r][c]));
            }
            #pragma unroll
            for (int mi = 0; mi < 2; mi++)
                #pragma unroll
                for (int nj = 0; nj < 4; nj++)
                    #pragma unroll
                    for (int h = 0; h < 2; h++) {
                        float* d = acc[mi][nj * 2 + h];
                        mma_bf16(d, ah[mi], bh[nj] + h * 2);   // hi*hi
                        mma_bf16(d, ah[mi], bl[nj] + h * 2);   // hi*lo
                        mma_bf16(d, al[mi], bh[nj] + h * 2);   // lo*hi
                    }
        }
        __syncthreads();                          // all warps done reading smem

        if (more) {
            #pragma unroll
            for (int q = 0; q < 2; q++) {
                int i = tid + q * 256;
                int row = i >> 2, c16 = i & 3;
                *(uint4*)&sA[0][row][c16 * 8] = rAh[q];
                *(uint4*)&sA[1][row][c16 * 8] = rAl[q];
            }
            #pragma unroll
            for (int q = 0; q < 2; q++) {
                int i = tid + q * 256;
                int row = i >> 4, c16 = i & 15;
                *(uint4*)&sB[0][row][c16 * 8] = rBh[q];
                *(uint4*)&sB[1][row][c16 * 8] = rBl[q];
            }
            __syncthreads();                      // smem ready for next block
        }
    }

    // epilogue: warp n-span 64 within one batch (HWSZ % 64 == 0)
    const int ng = n0 + wn;
    const int bb = ng / HWSZ;
    const int hwb = ng - bb * HWSZ + (lane & 3) * 2;
    const int rg = o0 + wm + (lane >> 2);
    #pragma unroll
    for (int mi = 0; mi < 2; mi++) {
        #pragma unroll
        for (int nf = 0; nf < 8; nf++) {
            const int hw = hwb + nf * 8;
            const float* d = acc[mi][nf];
            float* y0 = y + ((size_t)bb * COUT + rg + mi * 16) * HWSZ + hw;
            *(float2*)y0               = make_float2(d[0], d[1]);
            *(float2*)(y0 + 8 * HWSZ)  = make_float2(d[2], d[3]);
        }
    }
}

// ---------------------------------------------------------------------------
// GroupNorm stats + normalize (measured near DRAM roofline, unchanged)
// ---------------------------------------------------------------------------
__global__ __launch_bounds__(256)
void stats_kernel(const float* __restrict__ y)
{
    const int bg = blockIdx.x;
    const float4* p = (const float4*)(y + (size_t)bg * GELEMS);
    const int n4 = GELEMS / 4;
    float s = 0.0f, ss = 0.0f;
    for (int i = threadIdx.x; i < n4; i += 256) {
        float4 v = p[i];
        s  += (v.x + v.y) + (v.z + v.w);
        ss += (v.x * v.x + v.y * v.y) + (v.z * v.z + v.w * v.w);
    }
    #pragma unroll
    for (int o = 16; o > 0; o >>= 1) {
        s  += __shfl_down_sync(0xffffffffu, s, o);
        ss += __shfl_down_sync(0xffffffffu, ss, o);
    }
    __shared__ float ws[8], wss[8];
    const int lane = threadIdx.x & 31, wid = threadIdx.x >> 5;
    if (lane == 0) { ws[wid] = s; wss[wid] = ss; }
    __syncthreads();
    if (wid == 0) {
        s  = (lane < 8) ? ws[lane]  : 0.0f;
        ss = (lane < 8) ? wss[lane] : 0.0f;
        #pragma unroll
        for (int o = 4; o > 0; o >>= 1) {
            s  += __shfl_down_sync(0xffffffffu, s, o);
            ss += __shfl_down_sync(0xffffffffu, ss, o);
        }
        if (lane == 0) {
            const float inv_n = 1.0f / (float)GELEMS;
            float mean = s * inv_n;
            float var  = ss * inv_n - mean * mean;
            g_mean[bg] = mean;
            g_rstd[bg] = rsqrtf(var + EPS_GN);
        }
    }
}

__global__ __launch_bounds__(256)
void norm_kernel(float* __restrict__ y,
                 const float* __restrict__ gamma,
                 const float* __restrict__ beta)
{
    const size_t i4  = (size_t)blockIdx.x * 256 + threadIdx.x;
    const size_t idx = i4 * 4;
    const int o  = (int)((idx / HWSZ) % COUT);
    const int bg = (int)(idx / GELEMS);
    const float r  = g_rstd[bg];
    const float ga = gamma[o] * r;
    const float be = beta[o] - g_mean[bg] * ga;
    float4 v = *(float4*)(y + idx);
    v.x = fminf(fmaxf(fmaf(v.x, ga, be), HT_MIN), HT_MAX);
    v.y = fminf(fmaxf(fmaf(v.y, ga, be), HT_MIN), HT_MAX);
    v.z = fminf(fmaxf(fmaf(v.z, ga, be), HT_MIN), HT_MAX);
    v.w = fminf(fmaxf(fmaf(v.w, ga, be), HT_MIN), HT_MAX);
    *(float4*)(y + idx) = v;
}

// ---------------------------------------------------------------------------
extern "C" void kernel_launch(void* const* d_in, const int* in_sizes, int n_in,
                              void* d_out, int out_size)
{
    const float* x     = (const float*)d_in[0];
    const float* W     = (const float*)d_in[1];
    const float* gamma = (const float*)d_in[2];
    const float* beta  = (const float*)d_in[3];
    float* y = (float*)d_out;

    convert_w_kernel<<<COUT * CIN / 256, 256>>>(W);
    convert_x_kernel<<<dim3(NTOT / 256, CIN), 256>>>(x);
    gemm_mma_kernel<<<dim3(COUT / 128, NTOT / 128), 256>>>(y);
    stats_kernel<<<BATCH * NGRP, 256>>>(y);
    const size_t total4 = (size_t)BATCH * COUT * HWSZ / 4;
    norm_kernel<<<(unsigned)(total4 / 256), 256>>>(y, gamma, beta);
}

// round 13
// speedup vs baseline: 2.1338x; 1.2386x over previous
#include <cuda_runtime.h>
#include <cuda_bf16.h>
#include <math.h>
#include <cstdint>

// Problem constants
#define CIN   256
#define COUT  512
#define HWSZ  3136
#define BATCH 32
#define NTOT  (BATCH*HWSZ)   // 100352
#define NGRP  32
#define CPG   (COUT/NGRP)
#define GELEMS (CPG*HWSZ)
#define EPS_GN 1e-5f
#define HT_MIN -2.0f
#define HT_MAX  2.0f

// Device-global scratch
__device__ float g_mean[BATCH*NGRP];
__device__ float g_rstd[BATCH*NGRP];
__device__ __align__(16) __nv_bfloat16 g_w_hi[COUT*CIN];   // [o][c]
__device__ __align__(16) __nv_bfloat16 g_w_lo[COUT*CIN];

// ---------------- warp-level MMA helpers (sm_80+ baseline ISA) ----------------
__device__ __forceinline__ uint32_t smem_u32(const void* p) {
    uint32_t a;
    asm("{ .reg .u64 t; cvta.to.shared.u64 t, %1; cvt.u32.u64 %0, t; }" : "=r"(a) : "l"(p));
    return a;
}
__device__ __forceinline__ void ldsm_x4(uint32_t* r, uint32_t addr) {
    asm volatile("ldmatrix.sync.aligned.m8n8.x4.shared.b16 {%0,%1,%2,%3}, [%4];"
        : "=r"(r[0]), "=r"(r[1]), "=r"(r[2]), "=r"(r[3]) : "r"(addr));
}
__device__ __forceinline__ void ldsm_x4_t(uint32_t* r, uint32_t addr) {
    asm volatile("ldmatrix.sync.aligned.m8n8.x4.trans.shared.b16 {%0,%1,%2,%3}, [%4];"
        : "=r"(r[0]), "=r"(r[1]), "=r"(r[2]), "=r"(r[3]) : "r"(addr));
}
__device__ __forceinline__ void mma_bf16(float* d, const uint32_t* a, const uint32_t* b) {
    asm volatile("mma.sync.aligned.m16n8k16.row.col.f32.bf16.bf16.f32 "
        "{%0,%1,%2,%3}, {%4,%5,%6,%7}, {%8,%9}, {%0,%1,%2,%3};"
        : "+f"(d[0]), "+f"(d[1]), "+f"(d[2]), "+f"(d[3])
        : "r"(a[0]), "r"(a[1]), "r"(a[2]), "r"(a[3]), "r"(b[0]), "r"(b[1]));
}

// pack 2 floats -> bf16x2 hi and lo words
__device__ __forceinline__ void split2(float f0, float f1, uint32_t& hi, uint32_t& lo) {
    __nv_bfloat16 h0 = __float2bfloat16(f0);
    __nv_bfloat16 h1 = __float2bfloat16(f1);
    __nv_bfloat16 l0 = __float2bfloat16(f0 - __bfloat162float(h0));
    __nv_bfloat16 l1 = __float2bfloat16(f1 - __bfloat162float(h1));
    __nv_bfloat162 hp = __halves2bfloat162(h0, h1);
    __nv_bfloat162 lp = __halves2bfloat162(l0, l1);
    hi = *(uint32_t*)&hp;
    lo = *(uint32_t*)&lp;
}
__device__ __forceinline__ void split8(const float4 v0, const float4 v1,
                                       uint4& hi, uint4& lo) {
    split2(v0.x, v0.y, hi.x, lo.x);
    split2(v0.z, v0.w, hi.y, lo.y);
    split2(v1.x, v1.y, hi.z, lo.z);
    split2(v1.z, v1.w, hi.w, lo.w);
}

// ---------------------------------------------------------------------------
// W conversion: fp32 -> bf16 hi/lo (tiny, reused 784x -> keep as a pass)
// ---------------------------------------------------------------------------
__global__ void convert_w_kernel(const float* __restrict__ W) {
    int i = blockIdx.x * 256 + threadIdx.x;       // COUT*CIN = 131072
    float v = W[i];
    __nv_bfloat16 hi = __float2bfloat16(v);
    g_w_hi[i] = hi;
    g_w_lo[i] = __float2bfloat16(v - __bfloat162float(hi));
}

// ---------------------------------------------------------------------------
// Tensor-core GEMM via mma.sync: y[b,o,hw] = sum_c W[o,c]*x[b,c,hw]
// B tiles read DIRECTLY from fp32 x (native [b][c][hw] layout: n contiguous
// for fixed c); hi/lo split done in registers at STS time. No x relayout pass.
// CTA: 128(cout) x 128(spatial) x BK=32. 8 warps = 4(m) x 2(n).
// 3-pass split precision (hh + hl + lh). Register-prefetch pipeline.
// ---------------------------------------------------------------------------
#define PA 40    // A smem pitch (halves): 80B rows -> conflict-free ldmatrix
#define PB 136   // B smem pitch (halves): 272B rows -> conflict-free ldmatrix

__global__ __launch_bounds__(256, 1)
void gemm_mma_kernel(const float* __restrict__ x, float* __restrict__ y)
{
    __shared__ __align__(16) __nv_bfloat16 sA[2][128][PA];   // [prec][m][k]
    __shared__ __align__(16) __nv_bfloat16 sB[2][32][PB];    // [prec][k][n]

    const int tid  = threadIdx.x;
    const int lane = tid & 31;
    const int w    = tid >> 5;
    const int wm   = (w & 3) * 32;          // warp m offset (cout)
    const int wn   = (w >> 2) * 64;         // warp n offset (spatial)
    const int o0   = blockIdx.x * 128;      // cout tile (fast dim -> x reuse in L2)
    const int n0   = blockIdx.y * 128;      // spatial tile

    // B load coords: i = tid + q*256 -> row(c)=i>>4 (0..31), c16=i&15
    // each 8-elem chunk (n0 + c16*8 .. +7) stays within one batch (HWSZ%8==0)
    const int bn   = n0 + (tid & 15) * 8;
    const int bbB  = bn / HWSZ;
    const int hwB  = bn - bbB * HWSZ;
    const float* xbase = x + (size_t)bbB * CIN * HWSZ + hwB;   // + (c)*HWSZ

    float acc[2][8][4];
    #pragma unroll
    for (int i = 0; i < 2; i++)
        #pragma unroll
        for (int j = 0; j < 8; j++)
            #pragma unroll
            for (int q = 0; q < 4; q++) acc[i][j][q] = 0.0f;

    // ---- prologue: k-block 0 direct to smem ----
    #pragma unroll
    for (int q = 0; q < 2; q++) {
        int i = tid + q * 256;
        int row = i >> 2, c16 = i & 3;
        size_t ge = (size_t)(o0 + row) * CIN + c16 * 8;
        *(uint4*)&sA[0][row][c16 * 8] = *(const uint4*)(g_w_hi + ge);
        *(uint4*)&sA[1][row][c16 * 8] = *(const uint4*)(g_w_lo + ge);
    }
    #pragma unroll
    for (int q = 0; q < 2; q++) {
        int i = tid + q * 256;
        int row = i >> 4, c16 = i & 15;
        const float* xp = xbase + (size_t)row * HWSZ;
        float4 v0 = *(const float4*)(xp);
        float4 v1 = *(const float4*)(xp + 4);
        uint4 hi, lo;
        split8(v0, v1, hi, lo);
        *(uint4*)&sB[0][row][c16 * 8] = hi;
        *(uint4*)&sB[1][row][c16 * 8] = lo;
    }
    __syncthreads();

    for (int kb = 0; kb < CIN / 32; kb++) {
        const bool more = (kb + 1) < (CIN / 32);
        uint4 rAh[2], rAl[2];
        float4 rBv[2][2];
        if (more) {
            #pragma unroll
            for (int q = 0; q < 2; q++) {
                int i = tid + q * 256;
                int row = i >> 2, c16 = i & 3;
                size_t ge = (size_t)(o0 + row) * CIN + (kb + 1) * 32 + c16 * 8;
                rAh[q] = *(const uint4*)(g_w_hi + ge);
                rAl[q] = *(const uint4*)(g_w_lo + ge);
            }
            #pragma unroll
            for (int q = 0; q < 2; q++) {
                int i = tid + q * 256;
                int row = i >> 4;
                const float* xp = xbase + (size_t)((kb + 1) * 32 + row) * HWSZ;
                rBv[q][0] = *(const float4*)(xp);
                rBv[q][1] = *(const float4*)(xp + 4);
            }
        }

        #pragma unroll
        for (int ks = 0; ks < 2; ks++) {          // two k16 steps per block
            uint32_t ah[2][4], al[2][4];
            #pragma unroll
            for (int mi = 0; mi < 2; mi++) {
                const int r = wm + mi * 16 + (lane & 15);
                const int c = ks * 16 + (lane >> 4) * 8;
                ldsm_x4(ah[mi], smem_u32(&sA[0][r][c]));
                ldsm_x4(al[mi], smem_u32(&sA[1][r][c]));
            }
            uint32_t bh[4][4], bl[4][4];
            #pragma unroll
            for (int nj = 0; nj < 4; nj++) {      // 4 x n16 groups = warp n64
                const int r = ks * 16 + (lane & 15);
                const int c = wn + nj * 16 + (lane >> 4) * 8;
                ldsm_x4_t(bh[nj], smem_u32(&sB[0][r][c]));
                ldsm_x4_t(bl[nj], smem_u32(&sB[1][r][c]));
            }
            #pragma unroll
            for (int mi = 0; mi < 2; mi++)
                #pragma unroll
                for (int nj = 0; nj < 4; nj++)
                    #pragma unroll
                    for (int h = 0; h < 2; h++) {
                        float* d = acc[mi][nj * 2 + h];
                        mma_bf16(d, ah[mi], bh[nj] + h * 2);   // hi*hi
                        mma_bf16(d, ah[mi], bl[nj] + h * 2);   // hi*lo
                        mma_bf16(d, al[mi], bh[nj] + h * 2);   // lo*hi
                    }
        }
        __syncthreads();                          // all warps done reading smem

        if (more) {
            #pragma unroll
            for (int q = 0; q < 2; q++) {
                int i = tid + q * 256;
                int row = i >> 2, c16 = i & 3;
                *(uint4*)&sA[0][row][c16 * 8] = rAh[q];
                *(uint4*)&sA[1][row][c16 * 8] = rAl[q];
            }
            #pragma unroll
            for (int q = 0; q < 2; q++) {
                int i = tid + q * 256;
                int row = i >> 4, c16 = i & 15;
                uint4 hi, lo;
                split8(rBv[q][0], rBv[q][1], hi, lo);
                *(uint4*)&sB[0][row][c16 * 8] = hi;
                *(uint4*)&sB[1][row][c16 * 8] = lo;
            }
            __syncthreads();                      // smem ready for next block
        }
    }

    // epilogue: warp n-span 64 within one batch (HWSZ % 64 == 0)
    const int ng = n0 + wn;
    const int bb = ng / HWSZ;
    const int hwb = ng - bb * HWSZ + (lane & 3) * 2;
    const int rg = o0 + wm + (lane >> 2);
    #pragma unroll
    for (int mi = 0; mi < 2; mi++) {
        #pragma unroll
        for (int nf = 0; nf < 8; nf++) {
            const int hw = hwb + nf * 8;
            const float* d = acc[mi][nf];
            float* y0 = y + ((size_t)bb * COUT + rg + mi * 16) * HWSZ + hw;
            *(float2*)y0               = make_float2(d[0], d[1]);
            *(float2*)(y0 + 8 * HWSZ)  = make_float2(d[2], d[3]);
        }
    }
}

// ---------------------------------------------------------------------------
// GroupNorm stats + normalize (measured at DRAM roofline, unchanged)
// ---------------------------------------------------------------------------
__global__ __launch_bounds__(256)
void stats_kernel(const float* __restrict__ y)
{
    const int bg = blockIdx.x;
    const float4* p = (const float4*)(y + (size_t)bg * GELEMS);
    const int n4 = GELEMS / 4;
    float s = 0.0f, ss = 0.0f;
    for (int i = threadIdx.x; i < n4; i += 256) {
        float4 v = p[i];
        s  += (v.x + v.y) + (v.z + v.w);
        ss += (v.x * v.x + v.y * v.y) + (v.z * v.z + v.w * v.w);
    }
    #pragma unroll
    for (int o = 16; o > 0; o >>= 1) {
        s  += __shfl_down_sync(0xffffffffu, s, o);
        ss += __shfl_down_sync(0xffffffffu, ss, o);
    }
    __shared__ float ws[8], wss[8];
    const int lane = threadIdx.x & 31, wid = threadIdx.x >> 5;
    if (lane == 0) { ws[wid] = s; wss[wid] = ss; }
    __syncthreads();
    if (wid == 0) {
        s  = (lane < 8) ? ws[lane]  : 0.0f;
        ss = (lane < 8) ? wss[lane] : 0.0f;
        #pragma unroll
        for (int o = 4; o > 0; o >>= 1) {
            s  += __shfl_down_sync(0xffffffffu, s, o);
            ss += __shfl_down_sync(0xffffffffu, ss, o);
        }
        if (lane == 0) {
            const float inv_n = 1.0f / (float)GELEMS;
            float mean = s * inv_n;
            float var  = ss * inv_n - mean * mean;
            g_mean[bg] = mean;
            g_rstd[bg] = rsqrtf(var + EPS_GN);
        }
    }
}

__global__ __launch_bounds__(256)
void norm_kernel(float* __restrict__ y,
                 const float* __restrict__ gamma,
                 const float* __restrict__ beta)
{
    const size_t i4  = (size_t)blockIdx.x * 256 + threadIdx.x;
    const size_t idx = i4 * 4;
    const int o  = (int)((idx / HWSZ) % COUT);
    const int bg = (int)(idx / GELEMS);
    const float r  = g_rstd[bg];
    const float ga = gamma[o] * r;
    const float be = beta[o] - g_mean[bg] * ga;
    float4 v = *(float4*)(y + idx);
    v.x = fminf(fmaxf(fmaf(v.x, ga, be), HT_MIN), HT_MAX);
    v.y = fminf(fmaxf(fmaf(v.y, ga, be), HT_MIN), HT_MAX);
    v.z = fminf(fmaxf(fmaf(v.z, ga, be), HT_MIN), HT_MAX);
    v.w = fminf(fmaxf(fmaf(v.w, ga, be), HT_MIN), HT_MAX);
    *(float4*)(y + idx) = v;
}

// ---------------------------------------------------------------------------
extern "C" void kernel_launch(void* const* d_in, const int* in_sizes, int n_in,
                              void* d_out, int out_size)
{
    const float* x     = (const float*)d_in[0];
    const float* W     = (const float*)d_in[1];
    const float* gamma = (const float*)d_in[2];
    const float* beta  = (const float*)d_in[3];
    float* y = (float*)d_out;

    convert_w_kernel<<<COUT * CIN / 256, 256>>>(W);
    gemm_mma_kernel<<<dim3(COUT / 128, NTOT / 128), 256>>>(x, y);
    stats_kernel<<<BATCH * NGRP, 256>>>(y);
    const size_t total4 = (size_t)BATCH * COUT * HWSZ / 4;
    norm_kernel<<<(unsigned)(total4 / 256), 256>>>(y, gamma, beta);
}